// round 14
// baseline (speedup 1.0000x reference)
#include <cuda_runtime.h>
#include <cuda_fp16.h>
#include <math.h>
#include <stdint.h>

#define H 256
#define NB_MAX 4096
#define MAXT (4096 * 99)
#define TM 64            // tokens per CTA in mma kernels
#define SXH 264          // Xs smem row stride in halves
#define SWH 40           // W slab row stride in halves (80B rows, 16B-aligned)
#define KSH 32           // K-slab width in halves (2 k16-steps)
#define NSLAB 8          // 256 / KSH
#define SLABH (256 * SWH) // halves per W buffer
#define NTHR 256         // 8 warps

// ---- scratch (device-side only; never passed as launch args) ----
__device__ int    g_offs[NB_MAX + 1];
__device__ int    g_seg[MAXT];
__device__ float  g_mean[NB_MAX * H];
__device__ float  g_mg[NB_MAX * H];
__device__ float  g_posproj[201 * H];
__device__ __half g_Wpt[H * H];    // W_pos_top^T  [n][k]
__device__ __half g_Wpbt[H * H];   // W_pos_bot^T
__device__ __half g_W1t[H * H];
__device__ __half g_W2t[H * H];

// ---------------- PTX helpers ----------------
__device__ __forceinline__ void cp16(void* dst_smem, const void* src) {
    uint32_t d = (uint32_t)__cvta_generic_to_shared(dst_smem);
    asm volatile("cp.async.cg.shared.global [%0], [%1], 16;\n" :: "r"(d), "l"(src));
}
__device__ __forceinline__ void cp_commit() { asm volatile("cp.async.commit_group;\n"); }
__device__ __forceinline__ void cp_wait0()  { asm volatile("cp.async.wait_group 0;\n"); }
__device__ __forceinline__ void cp_wait1()  { asm volatile("cp.async.wait_group 1;\n"); }

__device__ __forceinline__ void mma_f16(float (&d)[4], const uint32_t (&a)[4],
                                        const uint32_t (&b)[2]) {
    asm volatile(
        "mma.sync.aligned.m16n8k16.row.col.f32.f16.f16.f32 "
        "{%0,%1,%2,%3}, {%4,%5,%6,%7}, {%8,%9}, {%0,%1,%2,%3};\n"
        : "+f"(d[0]), "+f"(d[1]), "+f"(d[2]), "+f"(d[3])
        : "r"(a[0]), "r"(a[1]), "r"(a[2]), "r"(a[3]), "r"(b[0]), "r"(b[1]));
}
__device__ __forceinline__ float fast_tanh(float x) {
    float r; asm("tanh.approx.f32 %0, %1;" : "=f"(r) : "f"(x)); return r;
}

// ---------------------------------------------------------------
// K1: exclusive prefix scan of seq_len -> g_offs
// ---------------------------------------------------------------
__global__ void k_scan(const int* __restrict__ seq_len, int nb) {
    __shared__ int chunk[1024];
    int tid = threadIdx.x;
    int base = tid * 4;
    int v0 = (base + 0 < nb) ? seq_len[base + 0] : 0;
    int v1 = (base + 1 < nb) ? seq_len[base + 1] : 0;
    int v2 = (base + 2 < nb) ? seq_len[base + 2] : 0;
    int v3 = (base + 3 < nb) ? seq_len[base + 3] : 0;
    int p1 = v0, p2 = v0 + v1, p3 = p2 + v2, p4 = p3 + v3;
    chunk[tid] = p4;
    __syncthreads();
    for (int d = 1; d < 1024; d <<= 1) {
        int t = (tid >= d) ? chunk[tid - d] : 0;
        __syncthreads();
        chunk[tid] += t;
        __syncthreads();
    }
    int prev = (tid > 0) ? chunk[tid - 1] : 0;
    if (base + 0 <= nb) g_offs[base + 0] = prev;
    if (base + 1 <= nb) g_offs[base + 1] = prev + p1;
    if (base + 2 <= nb) g_offs[base + 2] = prev + p2;
    if (base + 3 <= nb) g_offs[base + 3] = prev + p3;
    if (base + 4 <= nb) g_offs[base + 4] = prev + p4;
}

// ---------------------------------------------------------------
// K2: per-session mean + segment-id fill
// ---------------------------------------------------------------
__global__ void k_mean_seg(const float* __restrict__ hidden, int nb) {
    int b = blockIdx.x;
    if (b >= nb) return;
    int s = g_offs[b], e = g_offs[b + 1];
    int tid = threadIdx.x;
    float a[8];
    #pragma unroll
    for (int i = 0; i < 8; ++i) a[i] = 0.f;
    int t = s;
    for (; t + 7 < e; t += 8) {
        #pragma unroll
        for (int i = 0; i < 8; ++i) a[i] += hidden[(t + i) * H + tid];
    }
    for (; t < e; ++t) a[0] += hidden[t * H + tid];
    float acc = ((a[0] + a[1]) + (a[2] + a[3])) + ((a[4] + a[5]) + (a[6] + a[7]));
    g_mean[b * H + tid] = acc / (float)(e - s);
    for (int u = s + tid; u < e; u += blockDim.x) g_seg[u] = b;
}

// ---------------------------------------------------------------
// K2b: zero the output (harness poisons it)
// ---------------------------------------------------------------
__global__ void k_zero(float* __restrict__ out, int n) {
    int i = blockIdx.x * 256 + threadIdx.x;
    if (i < n) out[i] = 0.f;
}

// ---------------------------------------------------------------
// transpose + fp16-convert weights: dst[n][k] = (half)src[k][n]
// mats: 0=Wp_top, 1=Wp_bot, 2=W1, 3=W2
// ---------------------------------------------------------------
__global__ void k_transpose(const float* __restrict__ W_pos,
                            const float* __restrict__ W1,
                            const float* __restrict__ W2) {
    __shared__ float tile[32][33];
    int mat = blockIdx.y;
    const float* src = (mat == 0) ? W_pos
                     : (mat == 1) ? (W_pos + H * H)
                     : (mat == 2) ? W1 : W2;
    __half* dst = (mat == 0) ? g_Wpt
                : (mat == 1) ? g_Wpbt
                : (mat == 2) ? g_W1t : g_W2t;
    int bx = blockIdx.x & 7, by = blockIdx.x >> 3;
    int tx = threadIdx.x & 31, ty = threadIdx.x >> 5;
    #pragma unroll
    for (int i = 0; i < 4; ++i) {
        int r = by * 32 + ty + i * 8;
        tile[ty + i * 8][tx] = src[r * H + bx * 32 + tx];
    }
    __syncthreads();
    #pragma unroll
    for (int i = 0; i < 4; ++i) {
        int n = bx * 32 + ty + i * 8;
        dst[n * H + by * 32 + tx] = __float2half_rn(tile[tx][ty + i * 8]);
    }
}

// ---------------------------------------------------------------
// fp16 mma machinery: 8 warps as 2(row) x 4(col); warp tile 32x64
// W ring: 3 buffers of KSH=32 halves, prefetch distance 2
// ---------------------------------------------------------------
extern __shared__ __align__(16) char smem_dyn[];

__device__ __forceinline__ void stage_slab(__half* dst, const __half* __restrict__ Wt,
                                           int ksh, int tid) {
    #pragma unroll
    for (int i = 0; i < 4; ++i) {
        int idx = tid + i * NTHR;           // 0..1023
        int n = idx >> 2, c = idx & 3;      // 4 chunks of 8 halves per row
        cp16(dst + n * SWH + c * 8, Wt + n * H + ksh + c * 8);
    }
}

// full K=256 GEMM: acc += A[TM,256](half,smem) @ Wt^T (ring-streamed)
// entry: slab0 (+Xs) committed as one group, slab1 as a second group.
// exit: NOT synced (caller must __syncthreads before reusing As / ring).
__device__ __forceinline__ void gemm_h(const __half* __restrict__ As,
                                       const __half* __restrict__ Wt,
                                       __half* Wb,
                                       float acc[2][8][4],
                                       int tid, int lane, int R0, int C0) {
    const uint32_t* xp = (const uint32_t*)As;
    int arow = R0 + (lane >> 2);
    int kq2 = (lane & 3);
    int nb_ = C0 + (lane >> 2);
    #pragma unroll
    for (int s = 0; s < NSLAB; ++s) {
        if (s < NSLAB - 1) cp_wait1(); else cp_wait0();
        __syncthreads();
        if (s + 2 < NSLAB) {
            stage_slab(Wb + ((s + 2) % 3) * SLABH, Wt, (s + 2) * KSH, tid);
            cp_commit();
        }
        const uint32_t* wp = (const uint32_t*)(Wb + (s % 3) * SLABH);
        #pragma unroll
        for (int kk = 0; kk < 2; ++kk) {
            int k2 = (s * KSH + kk * 16) >> 1;
            uint32_t a[2][4];
            #pragma unroll
            for (int mt = 0; mt < 2; ++mt) {
                int r = arow + mt * 16;
                a[mt][0] = xp[r * (SXH / 2) + k2 + kq2];
                a[mt][1] = xp[(r + 8) * (SXH / 2) + k2 + kq2];
                a[mt][2] = xp[r * (SXH / 2) + k2 + kq2 + 4];
                a[mt][3] = xp[(r + 8) * (SXH / 2) + k2 + kq2 + 4];
            }
            int kl2 = (kk * 16) >> 1;
            uint32_t b[8][2];
            #pragma unroll
            for (int nt = 0; nt < 8; ++nt) {
                int n = nb_ + nt * 8;
                b[nt][0] = wp[n * (SWH / 2) + kl2 + kq2];
                b[nt][1] = wp[n * (SWH / 2) + kl2 + kq2 + 4];
            }
            #pragma unroll
            for (int mt = 0; mt < 2; ++mt)
                #pragma unroll
                for (int nt = 0; nt < 8; ++nt)
                    mma_f16(acc[mt][nt], a[mt], b[nt]);
        }
    }
}

__device__ __forceinline__ void zero_acc(float acc[2][8][4]) {
    #pragma unroll
    for (int mt = 0; mt < 2; ++mt)
        #pragma unroll
        for (int nt = 0; nt < 8; ++nt)
            #pragma unroll
            for (int j = 0; j < 4; ++j) acc[mt][nt][j] = 0.f;
}

// stage fp32 rows -> half tile (TM x 256 halves, stride SXH)
__device__ __forceinline__ void stage_x_h(__half* Xs, const float* __restrict__ src,
                                          int row_base, int nrows_clamp, int tid) {
    #pragma unroll
    for (int i = 0; i < 16; ++i) {
        int idx = tid + i * NTHR;            // 0..4095, 4 floats each
        int r = idx >> 6, c4 = (idx & 63) << 2;
        int sr = row_base + r;
        if (sr >= nrows_clamp) sr = nrows_clamp - 1;
        float4 v = *(const float4*)&src[(size_t)sr * H + c4];
        __half2 h01 = __floats2half2_rn(v.x, v.y);
        __half2 h23 = __floats2half2_rn(v.z, v.w);
        uint2 pk = make_uint2(*(uint32_t*)&h01, *(uint32_t*)&h23);
        *(uint2*)&Xs[r * SXH + c4] = pk;
    }
}

// ---------------------------------------------------------------
// K3: generic [rows,256]@[256,256]+bias GEMM.
// job 0: posproj = Aext(pos_table) @ Wp_bot^T + bias -> g_posproj
// job 1: mg      = g_mean          @ W1^T     + bias -> g_mg
// ---------------------------------------------------------------
__global__ __launch_bounds__(NTHR, 2) void k_gemm_bias(const float* __restrict__ Aext,
                                                       const float* __restrict__ bias,
                                                       int job, int nrows) {
    const float* A = (job == 0) ? Aext : g_mean;
    const __half* Wt = (job == 0) ? g_Wpbt : g_W1t;
    float* out = (job == 0) ? g_posproj : g_mg;

    __half* Xs = (__half*)smem_dyn;           // TM*SXH halves
    __half* Wb = Xs + TM * SXH;               // 3*SLABH halves
    int tid = threadIdx.x, lane = tid & 31, wid = tid >> 5;
    int R0 = (wid >> 2) * 32, C0 = (wid & 3) * 64;
    int rb = blockIdx.x * TM;

    stage_x_h(Xs, A, rb, nrows, tid);
    stage_slab(Wb, Wt, 0, tid);
    cp_commit();                               // group: Xs + slab0
    stage_slab(Wb + SLABH, Wt, KSH, tid);
    cp_commit();                               // group: slab1

    float acc[2][8][4];
    zero_acc(acc);
    gemm_h(Xs, Wt, Wb, acc, tid, lane, R0, C0);

    #pragma unroll
    for (int nt = 0; nt < 8; ++nt) {
        int c = C0 + nt * 8 + (lane & 3) * 2;
        float2 bv = *(const float2*)&bias[c];
        #pragma unroll
        for (int mt = 0; mt < 2; ++mt) {
            int r1 = rb + R0 + mt * 16 + (lane >> 2);
            int r2 = r1 + 8;
            if (r1 < nrows) {
                float2 o = make_float2(acc[mt][nt][0] + bv.x, acc[mt][nt][1] + bv.y);
                *(float2*)&out[(size_t)r1 * H + c] = o;
            }
            if (r2 < nrows) {
                float2 o = make_float2(acc[mt][nt][2] + bv.x, acc[mt][nt][3] + bv.y);
                *(float2*)&out[(size_t)r2 * H + c] = o;
            }
        }
    }
}

// ---------------------------------------------------------------
// K5: fused main kernel (fp16 mma) + fused finisher, TM=64, 2 CTAs/SM
// ---------------------------------------------------------------
__global__ __launch_bounds__(NTHR, 2) void k_main_mma(const float* __restrict__ hidden,
                                                      const float* __restrict__ b2,
                                                      const float* __restrict__ qw,
                                                      const float* __restrict__ qb,
                                                      const int* __restrict__ reverse_pos,
                                                      float* __restrict__ out,
                                                      int T) {
    __half* Xs = (__half*)smem_dyn;             // hidden tile -> PH tile
    __half* Wb = Xs + TM * SXH;                 // 3*SLABH halves
    float* partm   = (float*)(Wb + 3 * SLABH);  // TM*4
    float* alpha_s = partm + TM * 4;            // TM
    int*   rp_s    = (int*)(alpha_s + TM);      // TM
    int*   seg_s   = rp_s + TM;                 // TM

    int tid = threadIdx.x, lane = tid & 31, wid = tid >> 5;
    int R0 = (wid >> 2) * 32, C0 = (wid & 3) * 64;
    int t0 = blockIdx.x * TM;

    stage_x_h(Xs, hidden, t0, T, tid);
    stage_slab(Wb, g_Wpt, 0, tid);
    cp_commit();                                // group: Xs + slab0
    stage_slab(Wb + SLABH, g_Wpt, KSH, tid);
    cp_commit();                                // group: slab1
    if (tid < TM) {
        int t = t0 + tid;
        int tc = (t < T) ? t : T - 1;
        rp_s[tid]  = reverse_pos[tc];
        seg_s[tid] = g_seg[tc];
    }

    float acc[2][8][4];
    zero_acc(acc);

    // ---- GEMM A: X @ Wp_top ----
    gemm_h(Xs, g_Wpt, Wb, acc, tid, lane, R0, C0);
    __syncthreads();    // all warps done reading Xs + ring

    // pre-stage W2 slabs 0,1; epilogue A overlaps the loads
    stage_slab(Wb, g_W2t, 0, tid);
    cp_commit();
    stage_slab(Wb + SLABH, g_W2t, KSH, tid);
    cp_commit();

    // ---- epilogue A: tanh(acc + posproj[rp]) -> Xs (half) ----
    {
        int rowA = R0 + (lane >> 2);
        #pragma unroll
        for (int mt = 0; mt < 2; ++mt) {
            int r1 = rowA + mt * 16, r2 = r1 + 8;
            const float* pp1 = g_posproj + (size_t)rp_s[r1] * H;
            const float* pp2 = g_posproj + (size_t)rp_s[r2] * H;
            #pragma unroll
            for (int nt = 0; nt < 8; ++nt) {
                int c = C0 + nt * 8 + (lane & 3) * 2;
                float2 p1 = *(const float2*)&pp1[c];
                float2 p2 = *(const float2*)&pp2[c];
                __half2 h1 = __floats2half2_rn(fast_tanh(acc[mt][nt][0] + p1.x),
                                               fast_tanh(acc[mt][nt][1] + p1.y));
                __half2 h2 = __floats2half2_rn(fast_tanh(acc[mt][nt][2] + p2.x),
                                               fast_tanh(acc[mt][nt][3] + p2.y));
                *(uint32_t*)&Xs[r1 * SXH + c] = *(uint32_t*)&h1;
                *(uint32_t*)&Xs[r2 * SXH + c] = *(uint32_t*)&h2;
            }
        }
    }
    zero_acc(acc);

    // ---- GEMM B: PH @ W2 ---- (its first wait+sync orders the PH stores)
    gemm_h(Xs, g_W2t, Wb, acc, tid, lane, R0, C0);

    // ---- epilogue B: sigmoid(acc + b2 + mg[seg]) . qw -> alpha_s ----
    float ps[2][2];
    #pragma unroll
    for (int mt = 0; mt < 2; ++mt) { ps[mt][0] = 0.f; ps[mt][1] = 0.f; }
    int rowA = R0 + (lane >> 2);
    int sg[2][2];
    #pragma unroll
    for (int mt = 0; mt < 2; ++mt) {
        sg[mt][0] = seg_s[rowA + mt * 16];
        sg[mt][1] = seg_s[rowA + mt * 16 + 8];
    }
    #pragma unroll
    for (int nt = 0; nt < 8; ++nt) {
        int c = C0 + nt * 8 + (lane & 3) * 2;
        float2 bv = *(const float2*)&b2[c];
        float2 qv = *(const float2*)&qw[c];
        #pragma unroll
        for (int mt = 0; mt < 2; ++mt) {
            float2 m1 = *(const float2*)&g_mg[(size_t)sg[mt][0] * H + c];
            float2 m2 = *(const float2*)&g_mg[(size_t)sg[mt][1] * H + c];
            float z0 = acc[mt][nt][0] + bv.x + m1.x;
            float z1 = acc[mt][nt][1] + bv.y + m1.y;
            float z2 = acc[mt][nt][2] + bv.x + m2.x;
            float z3 = acc[mt][nt][3] + bv.y + m2.y;
            float g0 = 1.f / (1.f + __expf(-z0));
            float g1 = 1.f / (1.f + __expf(-z1));
            float g2 = 1.f / (1.f + __expf(-z2));
            float g3 = 1.f / (1.f + __expf(-z3));
            ps[mt][0] = fmaf(g0, qv.x, fmaf(g1, qv.y, ps[mt][0]));
            ps[mt][1] = fmaf(g2, qv.x, fmaf(g3, qv.y, ps[mt][1]));
        }
    }
    #pragma unroll
    for (int mt = 0; mt < 2; ++mt)
        #pragma unroll
        for (int hf = 0; hf < 2; ++hf) {
            ps[mt][hf] += __shfl_down_sync(0xffffffffu, ps[mt][hf], 2, 4);
            ps[mt][hf] += __shfl_down_sync(0xffffffffu, ps[mt][hf], 1, 4);
        }
    int cg = wid & 3;
    if ((lane & 3) == 0) {
        #pragma unroll
        for (int mt = 0; mt < 2; ++mt) {
            partm[(rowA + mt * 16) * 4 + cg]     = ps[mt][0];
            partm[(rowA + mt * 16 + 8) * 4 + cg] = ps[mt][1];
        }
    }
    __syncthreads();
    if (tid < TM) {
        float a = (partm[tid * 4 + 0] + partm[tid * 4 + 1]) +
                  (partm[tid * 4 + 2] + partm[tid * 4 + 3]);
        alpha_s[tid] = a + qb[0];
    }
    __syncthreads();

    // ---- fused finisher: out[seg] += alpha * hidden (fp32, from gmem) ----
    // thread owns column c=tid; coalesced row reads, flush on session change.
    {
        int c = tid;
        int nrows = T - t0; if (nrows > TM) nrows = TM;
        float accs = 0.f;
        int cur = seg_s[0];
        for (int rb_ = 0; rb_ < nrows; rb_ += 8) {
            int m = nrows - rb_; if (m > 8) m = 8;
            float hv[8];
            #pragma unroll
            for (int i = 0; i < 8; ++i)
                if (i < m) hv[i] = hidden[(size_t)(t0 + rb_ + i) * H + c];
            #pragma unroll
            for (int i = 0; i < 8; ++i) {
                if (i < m) {
                    int sgr = seg_s[rb_ + i];
                    if (sgr != cur) {
                        atomicAdd(&out[(size_t)cur * H + c], accs);
                        accs = 0.f;
                        cur = sgr;
                    }
                    accs = fmaf(alpha_s[rb_ + i], hv[i], accs);
                }
            }
        }
        atomicAdd(&out[(size_t)cur * H + c], accs);
    }
}

// ---------------------------------------------------------------
extern "C" void kernel_launch(void* const* d_in, const int* in_sizes, int n_in,
                              void* d_out, int out_size) {
    const float* hidden      = (const float*)d_in[0];
    const float* pos_table   = (const float*)d_in[1];
    const float* W_pos       = (const float*)d_in[2];
    const float* b_pos       = (const float*)d_in[3];
    const float* W1          = (const float*)d_in[4];
    const float* b1          = (const float*)d_in[5];
    const float* W2          = (const float*)d_in[6];
    const float* b2          = (const float*)d_in[7];
    const float* qw          = (const float*)d_in[8];
    const float* qb          = (const float*)d_in[9];
    const int*   seq_len     = (const int*)d_in[10];
    const int*   reverse_pos = (const int*)d_in[11];

    int T    = in_sizes[0] / H;
    int nb   = in_sizes[10];
    int npos = in_sizes[1] / H;

    size_t smem_gemm = (size_t)(TM * SXH + 3 * SLABH) * sizeof(__half);
    size_t smem_main = smem_gemm + (size_t)(TM * 5) * sizeof(float)
                     + (size_t)(2 * TM) * sizeof(int);
    cudaFuncSetAttribute(k_gemm_bias, cudaFuncAttributeMaxDynamicSharedMemorySize, (int)smem_gemm);
    cudaFuncSetAttribute(k_main_mma,  cudaFuncAttributeMaxDynamicSharedMemorySize, (int)smem_main);

    k_scan<<<1, 1024>>>(seq_len, nb);
    dim3 tg(64, 4);
    k_transpose<<<tg, 256>>>(W_pos, W1, W2);
    k_mean_seg<<<nb, H>>>(hidden, nb);
    k_zero<<<(out_size + 255) / 256, 256>>>((float*)d_out, out_size);
    // pos_proj = pos_table @ Wp_bot^T + b_pos   (job 0)
    k_gemm_bias<<<(npos + TM - 1) / TM, NTHR, smem_gemm>>>(pos_table, b_pos, 0, npos);
    // mg = mean @ W1^T + b1                     (job 1)
    k_gemm_bias<<<(nb + TM - 1) / TM, NTHR, smem_gemm>>>(pos_table, b1, 1, nb);
    k_main_mma<<<(T + TM - 1) / TM, NTHR, smem_main>>>(hidden, b2, qw, qb,
                                                       reverse_pos, (float*)d_out, T);
}

// round 15
// speedup vs baseline: 1.3487x; 1.3487x over previous
#include <cuda_runtime.h>
#include <cuda_fp16.h>
#include <math.h>
#include <stdint.h>

#define H 256
#define NB_MAX 4096
#define MAXT (4096 * 99)
#define TM 64            // tokens per CTA in mma kernels
#define SXH 264          // Xs smem row stride in halves
#define SWH 72           // W slab row stride in halves (144 B rows, 16B-aligned)
#define KSH 64           // K-slab width in halves (4 k16-steps)
#define NTHR 256         // 8 warps

// ---- scratch (device-side only; never passed as launch args) ----
__device__ int    g_offs[NB_MAX + 1];
__device__ int    g_seg[MAXT];
__device__ float  g_mean[NB_MAX * H];
__device__ float  g_mg[NB_MAX * H];
__device__ float  g_posproj[201 * H];
__device__ __half g_Wpt[H * H];    // W_pos_top^T  [n][k]
__device__ __half g_Wpbt[H * H];   // W_pos_bot^T
__device__ __half g_W1t[H * H];
__device__ __half g_W2t[H * H];

// ---------------- PTX helpers ----------------
__device__ __forceinline__ void cp16(void* dst_smem, const void* src) {
    uint32_t d = (uint32_t)__cvta_generic_to_shared(dst_smem);
    asm volatile("cp.async.cg.shared.global [%0], [%1], 16;\n" :: "r"(d), "l"(src));
}
__device__ __forceinline__ void cp_commit() { asm volatile("cp.async.commit_group;\n"); }
__device__ __forceinline__ void cp_wait0()  { asm volatile("cp.async.wait_group 0;\n"); }

__device__ __forceinline__ void mma_f16(float (&d)[4], const uint32_t (&a)[4],
                                        const uint32_t (&b)[2]) {
    asm volatile(
        "mma.sync.aligned.m16n8k16.row.col.f32.f16.f16.f32 "
        "{%0,%1,%2,%3}, {%4,%5,%6,%7}, {%8,%9}, {%0,%1,%2,%3};\n"
        : "+f"(d[0]), "+f"(d[1]), "+f"(d[2]), "+f"(d[3])
        : "r"(a[0]), "r"(a[1]), "r"(a[2]), "r"(a[3]), "r"(b[0]), "r"(b[1]));
}
__device__ __forceinline__ float fast_tanh(float x) {
    float r; asm("tanh.approx.f32 %0, %1;" : "=f"(r) : "f"(x)); return r;
}

// ---------------------------------------------------------------
// K1: exclusive prefix scan of seq_len -> g_offs
// ---------------------------------------------------------------
__global__ void k_scan(const int* __restrict__ seq_len, int nb) {
    __shared__ int chunk[1024];
    int tid = threadIdx.x;
    int base = tid * 4;
    int v0 = (base + 0 < nb) ? seq_len[base + 0] : 0;
    int v1 = (base + 1 < nb) ? seq_len[base + 1] : 0;
    int v2 = (base + 2 < nb) ? seq_len[base + 2] : 0;
    int v3 = (base + 3 < nb) ? seq_len[base + 3] : 0;
    int p1 = v0, p2 = v0 + v1, p3 = p2 + v2, p4 = p3 + v3;
    chunk[tid] = p4;
    __syncthreads();
    for (int d = 1; d < 1024; d <<= 1) {
        int t = (tid >= d) ? chunk[tid - d] : 0;
        __syncthreads();
        chunk[tid] += t;
        __syncthreads();
    }
    int prev = (tid > 0) ? chunk[tid - 1] : 0;
    if (base + 0 <= nb) g_offs[base + 0] = prev;
    if (base + 1 <= nb) g_offs[base + 1] = prev + p1;
    if (base + 2 <= nb) g_offs[base + 2] = prev + p2;
    if (base + 3 <= nb) g_offs[base + 3] = prev + p3;
    if (base + 4 <= nb) g_offs[base + 4] = prev + p4;
}

// ---------------------------------------------------------------
// K2: per-session mean + segment-id fill
// ---------------------------------------------------------------
__global__ void k_mean_seg(const float* __restrict__ hidden, int nb) {
    int b = blockIdx.x;
    if (b >= nb) return;
    int s = g_offs[b], e = g_offs[b + 1];
    int tid = threadIdx.x;
    float a[8];
    #pragma unroll
    for (int i = 0; i < 8; ++i) a[i] = 0.f;
    int t = s;
    for (; t + 7 < e; t += 8) {
        #pragma unroll
        for (int i = 0; i < 8; ++i) a[i] += hidden[(t + i) * H + tid];
    }
    for (; t < e; ++t) a[0] += hidden[t * H + tid];
    float acc = ((a[0] + a[1]) + (a[2] + a[3])) + ((a[4] + a[5]) + (a[6] + a[7]));
    g_mean[b * H + tid] = acc / (float)(e - s);
    for (int u = s + tid; u < e; u += blockDim.x) g_seg[u] = b;
}

// ---------------------------------------------------------------
// K2b: zero the output (harness poisons it)
// ---------------------------------------------------------------
__global__ void k_zero(float* __restrict__ out, int n) {
    int i = blockIdx.x * 256 + threadIdx.x;
    if (i < n) out[i] = 0.f;
}

// ---------------------------------------------------------------
// transpose + fp16-convert weights: dst[n][k] = (half)src[k][n]
// mats: 0=Wp_top, 1=Wp_bot, 2=W1, 3=W2
// ---------------------------------------------------------------
__global__ void k_transpose(const float* __restrict__ W_pos,
                            const float* __restrict__ W1,
                            const float* __restrict__ W2) {
    __shared__ float tile[32][33];
    int mat = blockIdx.y;
    const float* src = (mat == 0) ? W_pos
                     : (mat == 1) ? (W_pos + H * H)
                     : (mat == 2) ? W1 : W2;
    __half* dst = (mat == 0) ? g_Wpt
                : (mat == 1) ? g_Wpbt
                : (mat == 2) ? g_W1t : g_W2t;
    int bx = blockIdx.x & 7, by = blockIdx.x >> 3;
    int tx = threadIdx.x & 31, ty = threadIdx.x >> 5;
    #pragma unroll
    for (int i = 0; i < 4; ++i) {
        int r = by * 32 + ty + i * 8;
        tile[ty + i * 8][tx] = src[r * H + bx * 32 + tx];
    }
    __syncthreads();
    #pragma unroll
    for (int i = 0; i < 4; ++i) {
        int n = bx * 32 + ty + i * 8;
        dst[n * H + by * 32 + tx] = __float2half_rn(tile[tx][ty + i * 8]);
    }
}

// ---------------------------------------------------------------
// fp16 mma machinery: 8 warps as 2(row) x 4(col); warp tile 32x64
// slabs: KSH=64 halves wide, double-buffered (proven R10 pipeline)
// ---------------------------------------------------------------
extern __shared__ __align__(16) char smem_dyn[];

__device__ __forceinline__ void stage_slab(__half* dst, const __half* __restrict__ Wt,
                                           int ksh, int tid) {
    #pragma unroll
    for (int i = 0; i < 8; ++i) {
        int idx = tid + i * NTHR;           // 0..2047
        int n = idx >> 3, c = idx & 7;      // 8 chunks of 8 halves per row
        cp16(dst + n * SWH + c * 8, Wt + n * H + ksh + c * 8);
    }
}

// full K=256 GEMM: acc += A[TM,256](half,smem) @ Wt^T (slab-streamed)
// entry: slab 0 staged + synced. exit: fully synced.
__device__ __forceinline__ void gemm_h(const __half* __restrict__ As,
                                       const __half* __restrict__ Wt,
                                       __half* Ws0, __half* Ws1,
                                       float acc[2][8][4],
                                       int tid, int lane, int R0, int C0) {
    __half* bufs[2] = {Ws0, Ws1};
    const uint32_t* xp = (const uint32_t*)As;
    int arow = R0 + (lane >> 2);
    int kq2 = (lane & 3);
    int nb_ = C0 + (lane >> 2);
    for (int s = 0; s < 4; ++s) {
        const uint32_t* wp = (const uint32_t*)bufs[s & 1];
        if (s < 3) { stage_slab(bufs[(s + 1) & 1], Wt, (s + 1) * KSH, tid); cp_commit(); }
        #pragma unroll
        for (int kk = 0; kk < 4; ++kk) {
            int k2 = (s * KSH + kk * 16) >> 1;
            uint32_t a[2][4];
            #pragma unroll
            for (int mt = 0; mt < 2; ++mt) {
                int r = arow + mt * 16;
                a[mt][0] = xp[r * (SXH / 2) + k2 + kq2];
                a[mt][1] = xp[(r + 8) * (SXH / 2) + k2 + kq2];
                a[mt][2] = xp[r * (SXH / 2) + k2 + kq2 + 4];
                a[mt][3] = xp[(r + 8) * (SXH / 2) + k2 + kq2 + 4];
            }
            int kl2 = (kk * 16) >> 1;
            uint32_t b[8][2];
            #pragma unroll
            for (int nt = 0; nt < 8; ++nt) {
                int n = nb_ + nt * 8;
                b[nt][0] = wp[n * (SWH / 2) + kl2 + kq2];
                b[nt][1] = wp[n * (SWH / 2) + kl2 + kq2 + 4];
            }
            #pragma unroll
            for (int mt = 0; mt < 2; ++mt)
                #pragma unroll
                for (int nt = 0; nt < 8; ++nt)
                    mma_f16(acc[mt][nt], a[mt], b[nt]);
        }
        if (s < 3) cp_wait0();
        __syncthreads();
    }
}

__device__ __forceinline__ void zero_acc(float acc[2][8][4]) {
    #pragma unroll
    for (int mt = 0; mt < 2; ++mt)
        #pragma unroll
        for (int nt = 0; nt < 8; ++nt)
            #pragma unroll
            for (int j = 0; j < 4; ++j) acc[mt][nt][j] = 0.f;
}

// stage fp32 rows -> half tile (TM x 256 halves, stride SXH)
__device__ __forceinline__ void stage_x_h(__half* Xs, const float* __restrict__ src,
                                          int row_base, int nrows_clamp, int tid) {
    #pragma unroll
    for (int i = 0; i < 16; ++i) {
        int idx = tid + i * NTHR;            // 0..4095, 4 floats each
        int r = idx >> 6, c4 = (idx & 63) << 2;
        int sr = row_base + r;
        if (sr >= nrows_clamp) sr = nrows_clamp - 1;
        float4 v = *(const float4*)&src[(size_t)sr * H + c4];
        __half2 h01 = __floats2half2_rn(v.x, v.y);
        __half2 h23 = __floats2half2_rn(v.z, v.w);
        uint2 pk = make_uint2(*(uint32_t*)&h01, *(uint32_t*)&h23);
        *(uint2*)&Xs[r * SXH + c4] = pk;
    }
}

// ---------------------------------------------------------------
// K3: generic [rows,256]@[256,256]+bias GEMM.
// job 0: posproj = Aext(pos_table) @ Wp_bot^T + bias -> g_posproj
// job 1: mg      = g_mean          @ W1^T     + bias -> g_mg
// ---------------------------------------------------------------
__global__ __launch_bounds__(NTHR, 2) void k_gemm_bias(const float* __restrict__ Aext,
                                                       const float* __restrict__ bias,
                                                       int job, int nrows) {
    const float* A = (job == 0) ? Aext : g_mean;
    const __half* Wt = (job == 0) ? g_Wpbt : g_W1t;
    float* out = (job == 0) ? g_posproj : g_mg;

    __half* Xs  = (__half*)smem_dyn;          // TM*SXH halves
    __half* Ws0 = Xs + TM * SXH;              // 256*SWH halves
    __half* Ws1 = Ws0 + 256 * SWH;
    int tid = threadIdx.x, lane = tid & 31, wid = tid >> 5;
    int R0 = (wid >> 2) * 32, C0 = (wid & 3) * 64;
    int rb = blockIdx.x * TM;

    stage_x_h(Xs, A, rb, nrows, tid);
    stage_slab(Ws0, Wt, 0, tid);
    cp_commit(); cp_wait0();
    __syncthreads();

    float acc[2][8][4];
    zero_acc(acc);
    gemm_h(Xs, Wt, Ws0, Ws1, acc, tid, lane, R0, C0);

    #pragma unroll
    for (int nt = 0; nt < 8; ++nt) {
        int c = C0 + nt * 8 + (lane & 3) * 2;
        float2 bv = *(const float2*)&bias[c];
        #pragma unroll
        for (int mt = 0; mt < 2; ++mt) {
            int r1 = rb + R0 + mt * 16 + (lane >> 2);
            int r2 = r1 + 8;
            if (r1 < nrows) {
                float2 o = make_float2(acc[mt][nt][0] + bv.x, acc[mt][nt][1] + bv.y);
                *(float2*)&out[(size_t)r1 * H + c] = o;
            }
            if (r2 < nrows) {
                float2 o = make_float2(acc[mt][nt][2] + bv.x, acc[mt][nt][3] + bv.y);
                *(float2*)&out[(size_t)r2 * H + c] = o;
            }
        }
    }
}

// ---------------------------------------------------------------
// K5: fused main kernel (fp16 mma) + fused finisher, TM=64, 2 CTAs/SM
// ---------------------------------------------------------------
__global__ __launch_bounds__(NTHR, 2) void k_main_mma(const float* __restrict__ hidden,
                                                      const float* __restrict__ b2,
                                                      const float* __restrict__ qw,
                                                      const float* __restrict__ qb,
                                                      const int* __restrict__ reverse_pos,
                                                      float* __restrict__ out,
                                                      int T) {
    __half* Xs   = (__half*)smem_dyn;           // hidden tile -> PH tile
    __half* Ws0  = Xs + TM * SXH;
    __half* Ws1  = Ws0 + 256 * SWH;
    float* partm   = (float*)(Ws1 + 256 * SWH);  // TM*4
    float* alpha_s = partm + TM * 4;             // TM
    int*   rp_s    = (int*)(alpha_s + TM);       // TM
    int*   seg_s   = rp_s + TM;                  // TM

    int tid = threadIdx.x, lane = tid & 31, wid = tid >> 5;
    int R0 = (wid >> 2) * 32, C0 = (wid & 3) * 64;
    int t0 = blockIdx.x * TM;

    stage_x_h(Xs, hidden, t0, T, tid);
    stage_slab(Ws0, g_Wpt, 0, tid);
    cp_commit();
    if (tid < TM) {
        int t = t0 + tid;
        int tc = (t < T) ? t : T - 1;
        rp_s[tid]  = reverse_pos[tc];
        seg_s[tid] = g_seg[tc];
    }
    cp_wait0();
    __syncthreads();

    float acc[2][8][4];
    zero_acc(acc);

    // ---- GEMM A: X @ Wp_top ----
    gemm_h(Xs, g_Wpt, Ws0, Ws1, acc, tid, lane, R0, C0);

    // ---- epilogue A: tanh(acc + posproj[rp]) -> Xs (half); stage W2 slab0 ----
    stage_slab(Ws0, g_W2t, 0, tid);
    cp_commit();
    {
        int rowA = R0 + (lane >> 2);
        #pragma unroll
        for (int mt = 0; mt < 2; ++mt) {
            int r1 = rowA + mt * 16, r2 = r1 + 8;
            const float* pp1 = g_posproj + (size_t)rp_s[r1] * H;
            const float* pp2 = g_posproj + (size_t)rp_s[r2] * H;
            #pragma unroll
            for (int nt = 0; nt < 8; ++nt) {
                int c = C0 + nt * 8 + (lane & 3) * 2;
                float2 p1 = *(const float2*)&pp1[c];
                float2 p2 = *(const float2*)&pp2[c];
                __half2 h1 = __floats2half2_rn(fast_tanh(acc[mt][nt][0] + p1.x),
                                               fast_tanh(acc[mt][nt][1] + p1.y));
                __half2 h2 = __floats2half2_rn(fast_tanh(acc[mt][nt][2] + p2.x),
                                               fast_tanh(acc[mt][nt][3] + p2.y));
                *(uint32_t*)&Xs[r1 * SXH + c] = *(uint32_t*)&h1;
                *(uint32_t*)&Xs[r2 * SXH + c] = *(uint32_t*)&h2;
            }
        }
    }
    zero_acc(acc);
    cp_wait0();
    __syncthreads();

    // ---- GEMM B: PH @ W2 ----
    gemm_h(Xs, g_W2t, Ws0, Ws1, acc, tid, lane, R0, C0);

    // ---- epilogue B: sigmoid(acc + b2 + mg[seg]) . qw -> alpha_s ----
    float ps[2][2];
    #pragma unroll
    for (int mt = 0; mt < 2; ++mt) { ps[mt][0] = 0.f; ps[mt][1] = 0.f; }
    int rowA = R0 + (lane >> 2);
    int sg[2][2];
    #pragma unroll
    for (int mt = 0; mt < 2; ++mt) {
        sg[mt][0] = seg_s[rowA + mt * 16];
        sg[mt][1] = seg_s[rowA + mt * 16 + 8];
    }
    #pragma unroll
    for (int nt = 0; nt < 8; ++nt) {
        int c = C0 + nt * 8 + (lane & 3) * 2;
        float2 bv = *(const float2*)&b2[c];
        float2 qv = *(const float2*)&qw[c];
        #pragma unroll
        for (int mt = 0; mt < 2; ++mt) {
            float2 m1 = *(const float2*)&g_mg[(size_t)sg[mt][0] * H + c];
            float2 m2 = *(const float2*)&g_mg[(size_t)sg[mt][1] * H + c];
            float z0 = acc[mt][nt][0] + bv.x + m1.x;
            float z1 = acc[mt][nt][1] + bv.y + m1.y;
            float z2 = acc[mt][nt][2] + bv.x + m2.x;
            float z3 = acc[mt][nt][3] + bv.y + m2.y;
            float g0 = 1.f / (1.f + __expf(-z0));
            float g1 = 1.f / (1.f + __expf(-z1));
            float g2 = 1.f / (1.f + __expf(-z2));
            float g3 = 1.f / (1.f + __expf(-z3));
            ps[mt][0] = fmaf(g0, qv.x, fmaf(g1, qv.y, ps[mt][0]));
            ps[mt][1] = fmaf(g2, qv.x, fmaf(g3, qv.y, ps[mt][1]));
        }
    }
    #pragma unroll
    for (int mt = 0; mt < 2; ++mt)
        #pragma unroll
        for (int hf = 0; hf < 2; ++hf) {
            ps[mt][hf] += __shfl_down_sync(0xffffffffu, ps[mt][hf], 2, 4);
            ps[mt][hf] += __shfl_down_sync(0xffffffffu, ps[mt][hf], 1, 4);
        }
    int cg = wid & 3;
    if ((lane & 3) == 0) {
        #pragma unroll
        for (int mt = 0; mt < 2; ++mt) {
            partm[(rowA + mt * 16) * 4 + cg]     = ps[mt][0];
            partm[(rowA + mt * 16 + 8) * 4 + cg] = ps[mt][1];
        }
    }
    __syncthreads();
    if (tid < TM) {
        float a = (partm[tid * 4 + 0] + partm[tid * 4 + 1]) +
                  (partm[tid * 4 + 2] + partm[tid * 4 + 3]);
        alpha_s[tid] = a + qb[0];
    }
    __syncthreads();

    // ---- fused finisher: out[seg] += alpha * hidden (fp32, from gmem) ----
    // thread owns column c=tid; coalesced row reads, flush on session change.
    {
        int c = tid;
        int nrows = T - t0; if (nrows > TM) nrows = TM;
        float accs = 0.f;
        int cur = seg_s[0];
        for (int rb_ = 0; rb_ < nrows; rb_ += 8) {
            int m = nrows - rb_; if (m > 8) m = 8;
            float hv[8];
            #pragma unroll
            for (int i = 0; i < 8; ++i)
                if (i < m) hv[i] = hidden[(size_t)(t0 + rb_ + i) * H + c];
            #pragma unroll
            for (int i = 0; i < 8; ++i) {
                if (i < m) {
                    int sgr = seg_s[rb_ + i];
                    if (sgr != cur) {
                        atomicAdd(&out[(size_t)cur * H + c], accs);
                        accs = 0.f;
                        cur = sgr;
                    }
                    accs = fmaf(alpha_s[rb_ + i], hv[i], accs);
                }
            }
        }
        atomicAdd(&out[(size_t)cur * H + c], accs);
    }
}

// ---------------------------------------------------------------
extern "C" void kernel_launch(void* const* d_in, const int* in_sizes, int n_in,
                              void* d_out, int out_size) {
    const float* hidden      = (const float*)d_in[0];
    const float* pos_table   = (const float*)d_in[1];
    const float* W_pos       = (const float*)d_in[2];
    const float* b_pos       = (const float*)d_in[3];
    const float* W1          = (const float*)d_in[4];
    const float* b1          = (const float*)d_in[5];
    const float* W2          = (const float*)d_in[6];
    const float* b2          = (const float*)d_in[7];
    const float* qw          = (const float*)d_in[8];
    const float* qb          = (const float*)d_in[9];
    const int*   seq_len     = (const int*)d_in[10];
    const int*   reverse_pos = (const int*)d_in[11];

    int T    = in_sizes[0] / H;
    int nb   = in_sizes[10];
    int npos = in_sizes[1] / H;

    size_t smem_gemm = (size_t)(TM * SXH + 2 * 256 * SWH) * sizeof(__half);
    size_t smem_main = smem_gemm + (size_t)(TM * 5) * sizeof(float)
                     + (size_t)(2 * TM) * sizeof(int);
    cudaFuncSetAttribute(k_gemm_bias, cudaFuncAttributeMaxDynamicSharedMemorySize, (int)smem_gemm);
    cudaFuncSetAttribute(k_main_mma,  cudaFuncAttributeMaxDynamicSharedMemorySize, (int)smem_main);

    k_scan<<<1, 1024>>>(seq_len, nb);
    dim3 tg(64, 4);
    k_transpose<<<tg, 256>>>(W_pos, W1, W2);
    k_mean_seg<<<nb, H>>>(hidden, nb);
    k_zero<<<(out_size + 255) / 256, 256>>>((float*)d_out, out_size);
    // pos_proj = pos_table @ Wp_bot^T + b_pos   (job 0)
    k_gemm_bias<<<(npos + TM - 1) / TM, NTHR, smem_gemm>>>(pos_table, b_pos, 0, npos);
    // mg = mean @ W1^T + b1                     (job 1)
    k_gemm_bias<<<(nb + TM - 1) / TM, NTHR, smem_gemm>>>(pos_table, b1, 1, nb);
    k_main_mma<<<(T + TM - 1) / TM, NTHR, smem_main>>>(hidden, b2, qw, qb,
                                                       reverse_pos, (float*)d_out, T);
}

// round 16
// speedup vs baseline: 1.3841x; 1.0262x over previous
#include <cuda_runtime.h>
#include <cuda_fp16.h>
#include <math.h>
#include <stdint.h>

#define H 256
#define NB_MAX 4096
#define MAXT (4096 * 99)
#define TM 64            // tokens per CTA in mma kernels
#define SXH 264          // Xs smem row stride in halves
#define SWH 72           // W slab row stride in halves (144 B rows, 16B-aligned)
#define KSH 64           // K-slab width in halves (4 k16-steps)
#define NTHR 256         // 8 warps

// ---- scratch (device-side only; never passed as launch args) ----
__device__ int    g_offs[NB_MAX + 1];
__device__ int    g_seg[MAXT];
__device__ float  g_mean[NB_MAX * H];
__device__ float  g_mg[NB_MAX * H];
__device__ float  g_posproj[201 * H];
__device__ __half g_Wpt[H * H];    // W_pos_top^T  [n][k]
__device__ __half g_Wpbt[H * H];   // W_pos_bot^T
__device__ __half g_W1t[H * H];
__device__ __half g_W2t[H * H];

// ---------------- PTX helpers ----------------
__device__ __forceinline__ void cp16(void* dst_smem, const void* src) {
    uint32_t d = (uint32_t)__cvta_generic_to_shared(dst_smem);
    asm volatile("cp.async.cg.shared.global [%0], [%1], 16;\n" :: "r"(d), "l"(src));
}
__device__ __forceinline__ void cp_commit() { asm volatile("cp.async.commit_group;\n"); }
__device__ __forceinline__ void cp_wait0()  { asm volatile("cp.async.wait_group 0;\n"); }

__device__ __forceinline__ void mma_f16(float (&d)[4], const uint32_t (&a)[4],
                                        const uint32_t (&b)[2]) {
    asm volatile(
        "mma.sync.aligned.m16n8k16.row.col.f32.f16.f16.f32 "
        "{%0,%1,%2,%3}, {%4,%5,%6,%7}, {%8,%9}, {%0,%1,%2,%3};\n"
        : "+f"(d[0]), "+f"(d[1]), "+f"(d[2]), "+f"(d[3])
        : "r"(a[0]), "r"(a[1]), "r"(a[2]), "r"(a[3]), "r"(b[0]), "r"(b[1]));
}
__device__ __forceinline__ float fast_tanh(float x) {
    float r; asm("tanh.approx.f32 %0, %1;" : "=f"(r) : "f"(x)); return r;
}

// ---------------------------------------------------------------
// K1: exclusive prefix scan of seq_len -> g_offs
// ---------------------------------------------------------------
__global__ void k_scan(const int* __restrict__ seq_len, int nb) {
    __shared__ int chunk[1024];
    int tid = threadIdx.x;
    int base = tid * 4;
    int v0 = (base + 0 < nb) ? seq_len[base + 0] : 0;
    int v1 = (base + 1 < nb) ? seq_len[base + 1] : 0;
    int v2 = (base + 2 < nb) ? seq_len[base + 2] : 0;
    int v3 = (base + 3 < nb) ? seq_len[base + 3] : 0;
    int p1 = v0, p2 = v0 + v1, p3 = p2 + v2, p4 = p3 + v3;
    chunk[tid] = p4;
    __syncthreads();
    for (int d = 1; d < 1024; d <<= 1) {
        int t = (tid >= d) ? chunk[tid - d] : 0;
        __syncthreads();
        chunk[tid] += t;
        __syncthreads();
    }
    int prev = (tid > 0) ? chunk[tid - 1] : 0;
    if (base + 0 <= nb) g_offs[base + 0] = prev;
    if (base + 1 <= nb) g_offs[base + 1] = prev + p1;
    if (base + 2 <= nb) g_offs[base + 2] = prev + p2;
    if (base + 3 <= nb) g_offs[base + 3] = prev + p3;
    if (base + 4 <= nb) g_offs[base + 4] = prev + p4;
}

// ---------------------------------------------------------------
// K2: per-session mean + segment-id fill + zero out[b] (fused)
// ---------------------------------------------------------------
__global__ void k_mean_seg(const float* __restrict__ hidden,
                           float* __restrict__ out, int nb) {
    int b = blockIdx.x;
    if (b >= nb) return;
    int s = g_offs[b], e = g_offs[b + 1];
    int tid = threadIdx.x;
    out[(size_t)b * H + tid] = 0.f;     // fused k_zero (exact coverage: nb*H)
    float a[8];
    #pragma unroll
    for (int i = 0; i < 8; ++i) a[i] = 0.f;
    int t = s;
    for (; t + 7 < e; t += 8) {
        #pragma unroll
        for (int i = 0; i < 8; ++i) a[i] += hidden[(t + i) * H + tid];
    }
    for (; t < e; ++t) a[0] += hidden[t * H + tid];
    float acc = ((a[0] + a[1]) + (a[2] + a[3])) + ((a[4] + a[5]) + (a[6] + a[7]));
    g_mean[b * H + tid] = acc / (float)(e - s);
    for (int u = s + tid; u < e; u += blockDim.x) g_seg[u] = b;
}

// ---------------------------------------------------------------
// transpose + fp16-convert weights: dst[n][k] = (half)src[k][n]
// mats: 0=Wp_top, 1=Wp_bot, 2=W1, 3=W2
// ---------------------------------------------------------------
__global__ void k_transpose(const float* __restrict__ W_pos,
                            const float* __restrict__ W1,
                            const float* __restrict__ W2) {
    __shared__ float tile[32][33];
    int mat = blockIdx.y;
    const float* src = (mat == 0) ? W_pos
                     : (mat == 1) ? (W_pos + H * H)
                     : (mat == 2) ? W1 : W2;
    __half* dst = (mat == 0) ? g_Wpt
                : (mat == 1) ? g_Wpbt
                : (mat == 2) ? g_W1t : g_W2t;
    int bx = blockIdx.x & 7, by = blockIdx.x >> 3;
    int tx = threadIdx.x & 31, ty = threadIdx.x >> 5;
    #pragma unroll
    for (int i = 0; i < 4; ++i) {
        int r = by * 32 + ty + i * 8;
        tile[ty + i * 8][tx] = src[r * H + bx * 32 + tx];
    }
    __syncthreads();
    #pragma unroll
    for (int i = 0; i < 4; ++i) {
        int n = bx * 32 + ty + i * 8;
        dst[n * H + by * 32 + tx] = __float2half_rn(tile[tx][ty + i * 8]);
    }
}

// ---------------------------------------------------------------
// fp16 mma machinery: 8 warps as 2(row) x 4(col); warp tile 32x64
// slabs: KSH=64 halves wide, double-buffered (proven R10 pipeline)
// ---------------------------------------------------------------
extern __shared__ __align__(16) char smem_dyn[];

__device__ __forceinline__ void stage_slab(__half* dst, const __half* __restrict__ Wt,
                                           int ksh, int tid) {
    #pragma unroll
    for (int i = 0; i < 8; ++i) {
        int idx = tid + i * NTHR;           // 0..2047
        int n = idx >> 3, c = idx & 7;      // 8 chunks of 8 halves per row
        cp16(dst + n * SWH + c * 8, Wt + n * H + ksh + c * 8);
    }
}

// full K=256 GEMM: acc += A[TM,256](half,smem) @ Wt^T (slab-streamed)
// entry: slab 0 staged + synced. exit: fully synced.
__device__ __forceinline__ void gemm_h(const __half* __restrict__ As,
                                       const __half* __restrict__ Wt,
                                       __half* Ws0, __half* Ws1,
                                       float acc[2][8][4],
                                       int tid, int lane, int R0, int C0) {
    __half* bufs[2] = {Ws0, Ws1};
    const uint32_t* xp = (const uint32_t*)As;
    int arow = R0 + (lane >> 2);
    int kq2 = (lane & 3);
    int nb_ = C0 + (lane >> 2);
    for (int s = 0; s < 4; ++s) {
        const uint32_t* wp = (const uint32_t*)bufs[s & 1];
        if (s < 3) { stage_slab(bufs[(s + 1) & 1], Wt, (s + 1) * KSH, tid); cp_commit(); }
        #pragma unroll
        for (int kk = 0; kk < 4; ++kk) {
            int k2 = (s * KSH + kk * 16) >> 1;
            uint32_t a[2][4];
            #pragma unroll
            for (int mt = 0; mt < 2; ++mt) {
                int r = arow + mt * 16;
                a[mt][0] = xp[r * (SXH / 2) + k2 + kq2];
                a[mt][1] = xp[(r + 8) * (SXH / 2) + k2 + kq2];
                a[mt][2] = xp[r * (SXH / 2) + k2 + kq2 + 4];
                a[mt][3] = xp[(r + 8) * (SXH / 2) + k2 + kq2 + 4];
            }
            int kl2 = (kk * 16) >> 1;
            uint32_t b[8][2];
            #pragma unroll
            for (int nt = 0; nt < 8; ++nt) {
                int n = nb_ + nt * 8;
                b[nt][0] = wp[n * (SWH / 2) + kl2 + kq2];
                b[nt][1] = wp[n * (SWH / 2) + kl2 + kq2 + 4];
            }
            #pragma unroll
            for (int mt = 0; mt < 2; ++mt)
                #pragma unroll
                for (int nt = 0; nt < 8; ++nt)
                    mma_f16(acc[mt][nt], a[mt], b[nt]);
        }
        if (s < 3) cp_wait0();
        __syncthreads();
    }
}

__device__ __forceinline__ void zero_acc(float acc[2][8][4]) {
    #pragma unroll
    for (int mt = 0; mt < 2; ++mt)
        #pragma unroll
        for (int nt = 0; nt < 8; ++nt)
            #pragma unroll
            for (int j = 0; j < 4; ++j) acc[mt][nt][j] = 0.f;
}

// stage fp32 rows -> half tile (TM x 256 halves, stride SXH)
__device__ __forceinline__ void stage_x_h(__half* Xs, const float* __restrict__ src,
                                          int row_base, int nrows_clamp, int tid) {
    #pragma unroll
    for (int i = 0; i < 16; ++i) {
        int idx = tid + i * NTHR;            // 0..4095, 4 floats each
        int r = idx >> 6, c4 = (idx & 63) << 2;
        int sr = row_base + r;
        if (sr >= nrows_clamp) sr = nrows_clamp - 1;
        float4 v = *(const float4*)&src[(size_t)sr * H + c4];
        __half2 h01 = __floats2half2_rn(v.x, v.y);
        __half2 h23 = __floats2half2_rn(v.z, v.w);
        uint2 pk = make_uint2(*(uint32_t*)&h01, *(uint32_t*)&h23);
        *(uint2*)&Xs[r * SXH + c4] = pk;
    }
}

// ---------------------------------------------------------------
// K3: combined [rows,256]@[256,256]+bias GEMMs in ONE launch.
// blocks [0, nblk_mg)          : mg      = g_mean @ W1^T + b1 -> g_mg
// blocks [nblk_mg, +nblk_pp)   : posproj = pos_table @ Wp_bot^T + b_pos
// ---------------------------------------------------------------
__global__ __launch_bounds__(NTHR, 2) void k_gemm_bias2(const float* __restrict__ pos_table,
                                                        const float* __restrict__ b1,
                                                        const float* __restrict__ b_pos,
                                                        int nb, int npos, int nblk_mg) {
    int is_mg = (blockIdx.x < nblk_mg);
    const float* A    = is_mg ? g_mean : pos_table;
    const __half* Wt  = is_mg ? g_W1t  : g_Wpbt;
    const float* bias = is_mg ? b1     : b_pos;
    float* out        = is_mg ? g_mg   : g_posproj;
    int nrows         = is_mg ? nb     : npos;
    int rb = (is_mg ? blockIdx.x : (blockIdx.x - nblk_mg)) * TM;

    __half* Xs  = (__half*)smem_dyn;          // TM*SXH halves
    __half* Ws0 = Xs + TM * SXH;              // 256*SWH halves
    __half* Ws1 = Ws0 + 256 * SWH;
    int tid = threadIdx.x, lane = tid & 31, wid = tid >> 5;
    int R0 = (wid >> 2) * 32, C0 = (wid & 3) * 64;

    stage_x_h(Xs, A, rb, nrows, tid);
    stage_slab(Ws0, Wt, 0, tid);
    cp_commit(); cp_wait0();
    __syncthreads();

    float acc[2][8][4];
    zero_acc(acc);
    gemm_h(Xs, Wt, Ws0, Ws1, acc, tid, lane, R0, C0);

    #pragma unroll
    for (int nt = 0; nt < 8; ++nt) {
        int c = C0 + nt * 8 + (lane & 3) * 2;
        float2 bv = *(const float2*)&bias[c];
        #pragma unroll
        for (int mt = 0; mt < 2; ++mt) {
            int r1 = rb + R0 + mt * 16 + (lane >> 2);
            int r2 = r1 + 8;
            if (r1 < nrows) {
                float2 o = make_float2(acc[mt][nt][0] + bv.x, acc[mt][nt][1] + bv.y);
                *(float2*)&out[(size_t)r1 * H + c] = o;
            }
            if (r2 < nrows) {
                float2 o = make_float2(acc[mt][nt][2] + bv.x, acc[mt][nt][3] + bv.y);
                *(float2*)&out[(size_t)r2 * H + c] = o;
            }
        }
    }
}

// ---------------------------------------------------------------
// K5: fused main kernel (fp16 mma) + fused finisher, TM=64, 2 CTAs/SM
// ---------------------------------------------------------------
__global__ __launch_bounds__(NTHR, 2) void k_main_mma(const float* __restrict__ hidden,
                                                      const float* __restrict__ b2,
                                                      const float* __restrict__ qw,
                                                      const float* __restrict__ qb,
                                                      const int* __restrict__ reverse_pos,
                                                      float* __restrict__ out,
                                                      int T) {
    __half* Xs   = (__half*)smem_dyn;           // hidden tile -> PH tile
    __half* Ws0  = Xs + TM * SXH;
    __half* Ws1  = Ws0 + 256 * SWH;
    float* partm   = (float*)(Ws1 + 256 * SWH);  // TM*4
    float* alpha_s = partm + TM * 4;             // TM
    int*   rp_s    = (int*)(alpha_s + TM);       // TM
    int*   seg_s   = rp_s + TM;                  // TM

    int tid = threadIdx.x, lane = tid & 31, wid = tid >> 5;
    int R0 = (wid >> 2) * 32, C0 = (wid & 3) * 64;
    int t0 = blockIdx.x * TM;

    stage_x_h(Xs, hidden, t0, T, tid);
    stage_slab(Ws0, g_Wpt, 0, tid);
    cp_commit();
    if (tid < TM) {
        int t = t0 + tid;
        int tc = (t < T) ? t : T - 1;
        rp_s[tid]  = reverse_pos[tc];
        seg_s[tid] = g_seg[tc];
    }
    cp_wait0();
    __syncthreads();

    float acc[2][8][4];
    zero_acc(acc);

    // ---- GEMM A: X @ Wp_top ----
    gemm_h(Xs, g_Wpt, Ws0, Ws1, acc, tid, lane, R0, C0);

    // ---- epilogue A: tanh(acc + posproj[rp]) -> Xs (half); stage W2 slab0 ----
    stage_slab(Ws0, g_W2t, 0, tid);
    cp_commit();
    {
        int rowA = R0 + (lane >> 2);
        #pragma unroll
        for (int mt = 0; mt < 2; ++mt) {
            int r1 = rowA + mt * 16, r2 = r1 + 8;
            const float* pp1 = g_posproj + (size_t)rp_s[r1] * H;
            const float* pp2 = g_posproj + (size_t)rp_s[r2] * H;
            #pragma unroll
            for (int nt = 0; nt < 8; ++nt) {
                int c = C0 + nt * 8 + (lane & 3) * 2;
                float2 p1 = *(const float2*)&pp1[c];
                float2 p2 = *(const float2*)&pp2[c];
                __half2 h1 = __floats2half2_rn(fast_tanh(acc[mt][nt][0] + p1.x),
                                               fast_tanh(acc[mt][nt][1] + p1.y));
                __half2 h2 = __floats2half2_rn(fast_tanh(acc[mt][nt][2] + p2.x),
                                               fast_tanh(acc[mt][nt][3] + p2.y));
                *(uint32_t*)&Xs[r1 * SXH + c] = *(uint32_t*)&h1;
                *(uint32_t*)&Xs[r2 * SXH + c] = *(uint32_t*)&h2;
            }
        }
    }
    zero_acc(acc);
    cp_wait0();
    __syncthreads();

    // ---- GEMM B: PH @ W2 ----
    gemm_h(Xs, g_W2t, Ws0, Ws1, acc, tid, lane, R0, C0);

    // ---- epilogue B: sigmoid(acc + b2 + mg[seg]) . qw -> alpha_s ----
    float ps[2][2];
    #pragma unroll
    for (int mt = 0; mt < 2; ++mt) { ps[mt][0] = 0.f; ps[mt][1] = 0.f; }
    int rowA = R0 + (lane >> 2);
    int sg[2][2];
    #pragma unroll
    for (int mt = 0; mt < 2; ++mt) {
        sg[mt][0] = seg_s[rowA + mt * 16];
        sg[mt][1] = seg_s[rowA + mt * 16 + 8];
    }
    #pragma unroll
    for (int nt = 0; nt < 8; ++nt) {
        int c = C0 + nt * 8 + (lane & 3) * 2;
        float2 bv = *(const float2*)&b2[c];
        float2 qv = *(const float2*)&qw[c];
        #pragma unroll
        for (int mt = 0; mt < 2; ++mt) {
            float2 m1 = *(const float2*)&g_mg[(size_t)sg[mt][0] * H + c];
            float2 m2 = *(const float2*)&g_mg[(size_t)sg[mt][1] * H + c];
            float z0 = acc[mt][nt][0] + bv.x + m1.x;
            float z1 = acc[mt][nt][1] + bv.y + m1.y;
            float z2 = acc[mt][nt][2] + bv.x + m2.x;
            float z3 = acc[mt][nt][3] + bv.y + m2.y;
            float g0 = 1.f / (1.f + __expf(-z0));
            float g1 = 1.f / (1.f + __expf(-z1));
            float g2 = 1.f / (1.f + __expf(-z2));
            float g3 = 1.f / (1.f + __expf(-z3));
            ps[mt][0] = fmaf(g0, qv.x, fmaf(g1, qv.y, ps[mt][0]));
            ps[mt][1] = fmaf(g2, qv.x, fmaf(g3, qv.y, ps[mt][1]));
        }
    }
    #pragma unroll
    for (int mt = 0; mt < 2; ++mt)
        #pragma unroll
        for (int hf = 0; hf < 2; ++hf) {
            ps[mt][hf] += __shfl_down_sync(0xffffffffu, ps[mt][hf], 2, 4);
            ps[mt][hf] += __shfl_down_sync(0xffffffffu, ps[mt][hf], 1, 4);
        }
    int cg = wid & 3;
    if ((lane & 3) == 0) {
        #pragma unroll
        for (int mt = 0; mt < 2; ++mt) {
            partm[(rowA + mt * 16) * 4 + cg]     = ps[mt][0];
            partm[(rowA + mt * 16 + 8) * 4 + cg] = ps[mt][1];
        }
    }
    __syncthreads();
    if (tid < TM) {
        float a = (partm[tid * 4 + 0] + partm[tid * 4 + 1]) +
                  (partm[tid * 4 + 2] + partm[tid * 4 + 3]);
        alpha_s[tid] = a + qb[0];
    }
    __syncthreads();

    // ---- fused finisher: out[seg] += alpha * hidden (fp32, from gmem) ----
    {
        int c = tid;
        int nrows = T - t0; if (nrows > TM) nrows = TM;
        float accs = 0.f;
        int cur = seg_s[0];
        for (int rb_ = 0; rb_ < nrows; rb_ += 8) {
            int m = nrows - rb_; if (m > 8) m = 8;
            float hv[8];
            #pragma unroll
            for (int i = 0; i < 8; ++i)
                if (i < m) hv[i] = hidden[(size_t)(t0 + rb_ + i) * H + c];
            #pragma unroll
            for (int i = 0; i < 8; ++i) {
                if (i < m) {
                    int sgr = seg_s[rb_ + i];
                    if (sgr != cur) {
                        atomicAdd(&out[(size_t)cur * H + c], accs);
                        accs = 0.f;
                        cur = sgr;
                    }
                    accs = fmaf(alpha_s[rb_ + i], hv[i], accs);
                }
            }
        }
        atomicAdd(&out[(size_t)cur * H + c], accs);
    }
}

// ---------------------------------------------------------------
extern "C" void kernel_launch(void* const* d_in, const int* in_sizes, int n_in,
                              void* d_out, int out_size) {
    const float* hidden      = (const float*)d_in[0];
    const float* pos_table   = (const float*)d_in[1];
    const float* W_pos       = (const float*)d_in[2];
    const float* b_pos       = (const float*)d_in[3];
    const float* W1          = (const float*)d_in[4];
    const float* b1          = (const float*)d_in[5];
    const float* W2          = (const float*)d_in[6];
    const float* b2          = (const float*)d_in[7];
    const float* qw          = (const float*)d_in[8];
    const float* qb          = (const float*)d_in[9];
    const int*   seq_len     = (const int*)d_in[10];
    const int*   reverse_pos = (const int*)d_in[11];

    int T    = in_sizes[0] / H;
    int nb   = in_sizes[10];
    int npos = in_sizes[1] / H;

    size_t smem_gemm = (size_t)(TM * SXH + 2 * 256 * SWH) * sizeof(__half);
    size_t smem_main = smem_gemm + (size_t)(TM * 5) * sizeof(float)
                     + (size_t)(2 * TM) * sizeof(int);
    cudaFuncSetAttribute(k_gemm_bias2, cudaFuncAttributeMaxDynamicSharedMemorySize, (int)smem_gemm);
    cudaFuncSetAttribute(k_main_mma,   cudaFuncAttributeMaxDynamicSharedMemorySize, (int)smem_main);

    int nblk_mg = (nb + TM - 1) / TM;
    int nblk_pp = (npos + TM - 1) / TM;

    k_scan<<<1, 1024>>>(seq_len, nb);
    dim3 tg(64, 4);
    k_transpose<<<tg, 256>>>(W_pos, W1, W2);
    k_mean_seg<<<nb, H>>>(hidden, (float*)d_out, nb);
    // combined: mg = mean@W1^T+b1  AND  posproj = pos_table@Wp_bot^T+b_pos
    k_gemm_bias2<<<nblk_mg + nblk_pp, NTHR, smem_gemm>>>(pos_table, b1, b_pos,
                                                         nb, npos, nblk_mg);
    k_main_mma<<<(T + TM - 1) / TM, NTHR, smem_main>>>(hidden, b2, qw, qb,
                                                       reverse_pos, (float*)d_out, T);
}

// round 17
// speedup vs baseline: 1.5439x; 1.1155x over previous
#include <cuda_runtime.h>
#include <cuda_fp16.h>
#include <math.h>
#include <stdint.h>

#define H 256
#define NB_MAX 4096
#define MAXT (4096 * 99)
#define TM 64            // tokens per CTA in mma kernels
#define SXH 264          // Xs smem row stride in halves
#define SWH 72           // W slab row stride in halves (144 B rows, 16B-aligned)
#define KSH 64           // K-slab width in halves (4 k16-steps)
#define NTHR 256         // 8 warps

// ---- scratch (device-side only; never passed as launch args) ----
__device__ int    g_offs[NB_MAX + 1];
__device__ int    g_seg[MAXT];
__device__ float  g_mean[NB_MAX * H];
__device__ float  g_mg[NB_MAX * H];
__device__ float  g_posproj[201 * H];
__device__ __half g_Wpt[H * H];    // W_pos_top^T  [n][k]
__device__ __half g_Wpbt[H * H];   // W_pos_bot^T
__device__ __half g_W1t[H * H];
__device__ __half g_W2t[H * H];

// ---------------- PTX helpers ----------------
__device__ __forceinline__ void cp16(void* dst_smem, const void* src) {
    uint32_t d = (uint32_t)__cvta_generic_to_shared(dst_smem);
    asm volatile("cp.async.cg.shared.global [%0], [%1], 16;\n" :: "r"(d), "l"(src));
}
__device__ __forceinline__ void cp_commit() { asm volatile("cp.async.commit_group;\n"); }
__device__ __forceinline__ void cp_wait0()  { asm volatile("cp.async.wait_group 0;\n"); }

__device__ __forceinline__ void mma_f16(float (&d)[4], const uint32_t (&a)[4],
                                        const uint32_t (&b)[2]) {
    asm volatile(
        "mma.sync.aligned.m16n8k16.row.col.f32.f16.f16.f32 "
        "{%0,%1,%2,%3}, {%4,%5,%6,%7}, {%8,%9}, {%0,%1,%2,%3};\n"
        : "+f"(d[0]), "+f"(d[1]), "+f"(d[2]), "+f"(d[3])
        : "r"(a[0]), "r"(a[1]), "r"(a[2]), "r"(a[3]), "r"(b[0]), "r"(b[1]));
}
__device__ __forceinline__ void ldsm_x4(uint32_t& r0, uint32_t& r1,
                                        uint32_t& r2, uint32_t& r3, uint32_t addr) {
    asm volatile("ldmatrix.sync.aligned.m8n8.x4.shared.b16 {%0,%1,%2,%3}, [%4];"
                 : "=r"(r0), "=r"(r1), "=r"(r2), "=r"(r3) : "r"(addr));
}
__device__ __forceinline__ float fast_tanh(float x) {
    float r; asm("tanh.approx.f32 %0, %1;" : "=f"(r) : "f"(x)); return r;
}

// ---------------------------------------------------------------
// K1: exclusive prefix scan of seq_len -> g_offs
// ---------------------------------------------------------------
__global__ void k_scan(const int* __restrict__ seq_len, int nb) {
    __shared__ int chunk[1024];
    int tid = threadIdx.x;
    int base = tid * 4;
    int v0 = (base + 0 < nb) ? seq_len[base + 0] : 0;
    int v1 = (base + 1 < nb) ? seq_len[base + 1] : 0;
    int v2 = (base + 2 < nb) ? seq_len[base + 2] : 0;
    int v3 = (base + 3 < nb) ? seq_len[base + 3] : 0;
    int p1 = v0, p2 = v0 + v1, p3 = p2 + v2, p4 = p3 + v3;
    chunk[tid] = p4;
    __syncthreads();
    for (int d = 1; d < 1024; d <<= 1) {
        int t = (tid >= d) ? chunk[tid - d] : 0;
        __syncthreads();
        chunk[tid] += t;
        __syncthreads();
    }
    int prev = (tid > 0) ? chunk[tid - 1] : 0;
    if (base + 0 <= nb) g_offs[base + 0] = prev;
    if (base + 1 <= nb) g_offs[base + 1] = prev + p1;
    if (base + 2 <= nb) g_offs[base + 2] = prev + p2;
    if (base + 3 <= nb) g_offs[base + 3] = prev + p3;
    if (base + 4 <= nb) g_offs[base + 4] = prev + p4;
}

// ---------------------------------------------------------------
// K2: per-session mean + segment-id fill + zero out[b] (fused)
// ---------------------------------------------------------------
__global__ void k_mean_seg(const float* __restrict__ hidden,
                           float* __restrict__ out, int nb) {
    int b = blockIdx.x;
    if (b >= nb) return;
    int s = g_offs[b], e = g_offs[b + 1];
    int tid = threadIdx.x;
    out[(size_t)b * H + tid] = 0.f;     // fused k_zero (exact coverage: nb*H)
    float a[8];
    #pragma unroll
    for (int i = 0; i < 8; ++i) a[i] = 0.f;
    int t = s;
    for (; t + 7 < e; t += 8) {
        #pragma unroll
        for (int i = 0; i < 8; ++i) a[i] += hidden[(t + i) * H + tid];
    }
    for (; t < e; ++t) a[0] += hidden[t * H + tid];
    float acc = ((a[0] + a[1]) + (a[2] + a[3])) + ((a[4] + a[5]) + (a[6] + a[7]));
    g_mean[b * H + tid] = acc / (float)(e - s);
    for (int u = s + tid; u < e; u += blockDim.x) g_seg[u] = b;
}

// ---------------------------------------------------------------
// transpose + fp16-convert weights: dst[n][k] = (half)src[k][n]
// mats: 0=Wp_top, 1=Wp_bot, 2=W1, 3=W2
// ---------------------------------------------------------------
__global__ void k_transpose(const float* __restrict__ W_pos,
                            const float* __restrict__ W1,
                            const float* __restrict__ W2) {
    __shared__ float tile[32][33];
    int mat = blockIdx.y;
    const float* src = (mat == 0) ? W_pos
                     : (mat == 1) ? (W_pos + H * H)
                     : (mat == 2) ? W1 : W2;
    __half* dst = (mat == 0) ? g_Wpt
                : (mat == 1) ? g_Wpbt
                : (mat == 2) ? g_W1t : g_W2t;
    int bx = blockIdx.x & 7, by = blockIdx.x >> 3;
    int tx = threadIdx.x & 31, ty = threadIdx.x >> 5;
    #pragma unroll
    for (int i = 0; i < 4; ++i) {
        int r = by * 32 + ty + i * 8;
        tile[ty + i * 8][tx] = src[r * H + bx * 32 + tx];
    }
    __syncthreads();
    #pragma unroll
    for (int i = 0; i < 4; ++i) {
        int n = bx * 32 + ty + i * 8;
        dst[n * H + by * 32 + tx] = __float2half_rn(tile[tx][ty + i * 8]);
    }
}

// ---------------------------------------------------------------
// fp16 mma machinery: 8 warps as 2(row) x 4(col); warp tile 32x64
// slabs: KSH=64 halves wide, double-buffered; LDSM fragment loads
// ---------------------------------------------------------------
extern __shared__ __align__(16) char smem_dyn[];

__device__ __forceinline__ void stage_slab(__half* dst, const __half* __restrict__ Wt,
                                           int ksh, int tid) {
    #pragma unroll
    for (int i = 0; i < 8; ++i) {
        int idx = tid + i * NTHR;           // 0..2047
        int n = idx >> 3, c = idx & 7;      // 8 chunks of 8 halves per row
        cp16(dst + n * SWH + c * 8, Wt + n * H + ksh + c * 8);
    }
}

// full K=256 GEMM: acc += A[TM,256](half,smem) @ Wt^T (slab-streamed)
// entry: slab 0 staged + synced. exit: fully synced.
__device__ __forceinline__ void gemm_h(const __half* __restrict__ As,
                                       const __half* __restrict__ Wt,
                                       __half* Ws0, __half* Ws1,
                                       float acc[2][8][4],
                                       int tid, int lane, int R0, int C0) {
    __half* bufs[2] = {Ws0, Ws1};
    uint32_t xs_base = (uint32_t)__cvta_generic_to_shared(As);
    uint32_t wb_base[2] = {(uint32_t)__cvta_generic_to_shared(Ws0),
                           (uint32_t)__cvta_generic_to_shared(Ws1)};
    // ldmatrix lane-address offsets (bytes)
    uint32_t a_off[2], b_off[4];
    #pragma unroll
    for (int mt = 0; mt < 2; ++mt)
        a_off[mt] = (uint32_t)(((R0 + mt * 16 + (lane & 15)) * SXH
                               + ((lane >> 4) << 3)) * 2);
    #pragma unroll
    for (int p = 0; p < 4; ++p)
        b_off[p] = (uint32_t)(((C0 + p * 16 + (lane & 7) + ((lane >> 4) << 3)) * SWH
                              + (((lane >> 3) & 1) << 3)) * 2);

    for (int s = 0; s < 4; ++s) {
        if (s < 3) { stage_slab(bufs[(s + 1) & 1], Wt, (s + 1) * KSH, tid); cp_commit(); }
        uint32_t wbb = wb_base[s & 1];
        #pragma unroll
        for (int kk = 0; kk < 4; ++kk) {
            uint32_t ka = (uint32_t)((s * KSH + kk * 16) * 2);
            uint32_t kb = (uint32_t)(kk * 32);
            uint32_t a[2][4];
            #pragma unroll
            for (int mt = 0; mt < 2; ++mt)
                ldsm_x4(a[mt][0], a[mt][1], a[mt][2], a[mt][3],
                        xs_base + a_off[mt] + ka);
            uint32_t b[8][2];
            #pragma unroll
            for (int p = 0; p < 4; ++p)
                ldsm_x4(b[2 * p][0], b[2 * p][1], b[2 * p + 1][0], b[2 * p + 1][1],
                        wbb + b_off[p] + kb);
            #pragma unroll
            for (int mt = 0; mt < 2; ++mt)
                #pragma unroll
                for (int nt = 0; nt < 8; ++nt)
                    mma_f16(acc[mt][nt], a[mt], b[nt]);
        }
        if (s < 3) cp_wait0();
        __syncthreads();
    }
}

__device__ __forceinline__ void zero_acc(float acc[2][8][4]) {
    #pragma unroll
    for (int mt = 0; mt < 2; ++mt)
        #pragma unroll
        for (int nt = 0; nt < 8; ++nt)
            #pragma unroll
            for (int j = 0; j < 4; ++j) acc[mt][nt][j] = 0.f;
}

// stage fp32 rows -> half tile (TM x 256 halves, stride SXH)
__device__ __forceinline__ void stage_x_h(__half* Xs, const float* __restrict__ src,
                                          int row_base, int nrows_clamp, int tid) {
    #pragma unroll
    for (int i = 0; i < 16; ++i) {
        int idx = tid + i * NTHR;            // 0..4095, 4 floats each
        int r = idx >> 6, c4 = (idx & 63) << 2;
        int sr = row_base + r;
        if (sr >= nrows_clamp) sr = nrows_clamp - 1;
        float4 v = *(const float4*)&src[(size_t)sr * H + c4];
        __half2 h01 = __floats2half2_rn(v.x, v.y);
        __half2 h23 = __floats2half2_rn(v.z, v.w);
        uint2 pk = make_uint2(*(uint32_t*)&h01, *(uint32_t*)&h23);
        *(uint2*)&Xs[r * SXH + c4] = pk;
    }
}

// ---------------------------------------------------------------
// K3: combined [rows,256]@[256,256]+bias GEMMs in ONE launch.
// blocks [0, nblk_mg)          : mg      = g_mean @ W1^T + b1 -> g_mg
// blocks [nblk_mg, +nblk_pp)   : posproj = pos_table @ Wp_bot^T + b_pos
// ---------------------------------------------------------------
__global__ __launch_bounds__(NTHR, 2) void k_gemm_bias2(const float* __restrict__ pos_table,
                                                        const float* __restrict__ b1,
                                                        const float* __restrict__ b_pos,
                                                        int nb, int npos, int nblk_mg) {
    int is_mg = (blockIdx.x < nblk_mg);
    const float* A    = is_mg ? g_mean : pos_table;
    const __half* Wt  = is_mg ? g_W1t  : g_Wpbt;
    const float* bias = is_mg ? b1     : b_pos;
    float* out        = is_mg ? g_mg   : g_posproj;
    int nrows         = is_mg ? nb     : npos;
    int rb = (is_mg ? blockIdx.x : (blockIdx.x - nblk_mg)) * TM;

    __half* Xs  = (__half*)smem_dyn;          // TM*SXH halves
    __half* Ws0 = Xs + TM * SXH;              // 256*SWH halves
    __half* Ws1 = Ws0 + 256 * SWH;
    int tid = threadIdx.x, lane = tid & 31, wid = tid >> 5;
    int R0 = (wid >> 2) * 32, C0 = (wid & 3) * 64;

    stage_x_h(Xs, A, rb, nrows, tid);
    stage_slab(Ws0, Wt, 0, tid);
    cp_commit(); cp_wait0();
    __syncthreads();

    float acc[2][8][4];
    zero_acc(acc);
    gemm_h(Xs, Wt, Ws0, Ws1, acc, tid, lane, R0, C0);

    #pragma unroll
    for (int nt = 0; nt < 8; ++nt) {
        int c = C0 + nt * 8 + (lane & 3) * 2;
        float2 bv = *(const float2*)&bias[c];
        #pragma unroll
        for (int mt = 0; mt < 2; ++mt) {
            int r1 = rb + R0 + mt * 16 + (lane >> 2);
            int r2 = r1 + 8;
            if (r1 < nrows) {
                float2 o = make_float2(acc[mt][nt][0] + bv.x, acc[mt][nt][1] + bv.y);
                *(float2*)&out[(size_t)r1 * H + c] = o;
            }
            if (r2 < nrows) {
                float2 o = make_float2(acc[mt][nt][2] + bv.x, acc[mt][nt][3] + bv.y);
                *(float2*)&out[(size_t)r2 * H + c] = o;
            }
        }
    }
}

// ---------------------------------------------------------------
// K5: fused main kernel (fp16 mma) + fused finisher, TM=64, 2 CTAs/SM
// ---------------------------------------------------------------
__global__ __launch_bounds__(NTHR, 2) void k_main_mma(const float* __restrict__ hidden,
                                                      const float* __restrict__ b2,
                                                      const float* __restrict__ qw,
                                                      const float* __restrict__ qb,
                                                      const int* __restrict__ reverse_pos,
                                                      float* __restrict__ out,
                                                      int T) {
    __half* Xs   = (__half*)smem_dyn;           // hidden tile -> PH tile
    __half* Ws0  = Xs + TM * SXH;
    __half* Ws1  = Ws0 + 256 * SWH;
    float* partm   = (float*)(Ws1 + 256 * SWH);  // TM*4
    float* alpha_s = partm + TM * 4;             // TM
    int*   rp_s    = (int*)(alpha_s + TM);       // TM
    int*   seg_s   = rp_s + TM;                  // TM

    int tid = threadIdx.x, lane = tid & 31, wid = tid >> 5;
    int R0 = (wid >> 2) * 32, C0 = (wid & 3) * 64;
    int t0 = blockIdx.x * TM;

    stage_x_h(Xs, hidden, t0, T, tid);
    stage_slab(Ws0, g_Wpt, 0, tid);
    cp_commit();
    if (tid < TM) {
        int t = t0 + tid;
        int tc = (t < T) ? t : T - 1;
        rp_s[tid]  = reverse_pos[tc];
        seg_s[tid] = g_seg[tc];
    }
    cp_wait0();
    __syncthreads();

    float acc[2][8][4];
    zero_acc(acc);

    // ---- GEMM A: X @ Wp_top ----
    gemm_h(Xs, g_Wpt, Ws0, Ws1, acc, tid, lane, R0, C0);

    // ---- epilogue A: tanh(acc + posproj[rp]) -> Xs (half); stage W2 slab0 ----
    stage_slab(Ws0, g_W2t, 0, tid);
    cp_commit();
    {
        int rowA = R0 + (lane >> 2);
        #pragma unroll
        for (int mt = 0; mt < 2; ++mt) {
            int r1 = rowA + mt * 16, r2 = r1 + 8;
            const float* pp1 = g_posproj + (size_t)rp_s[r1] * H;
            const float* pp2 = g_posproj + (size_t)rp_s[r2] * H;
            #pragma unroll
            for (int nt = 0; nt < 8; ++nt) {
                int c = C0 + nt * 8 + (lane & 3) * 2;
                float2 p1 = *(const float2*)&pp1[c];
                float2 p2 = *(const float2*)&pp2[c];
                __half2 h1 = __floats2half2_rn(fast_tanh(acc[mt][nt][0] + p1.x),
                                               fast_tanh(acc[mt][nt][1] + p1.y));
                __half2 h2 = __floats2half2_rn(fast_tanh(acc[mt][nt][2] + p2.x),
                                               fast_tanh(acc[mt][nt][3] + p2.y));
                *(uint32_t*)&Xs[r1 * SXH + c] = *(uint32_t*)&h1;
                *(uint32_t*)&Xs[r2 * SXH + c] = *(uint32_t*)&h2;
            }
        }
    }
    zero_acc(acc);
    cp_wait0();
    __syncthreads();

    // ---- GEMM B: PH @ W2 ----
    gemm_h(Xs, g_W2t, Ws0, Ws1, acc, tid, lane, R0, C0);

    // ---- epilogue B: sigmoid(acc + b2 + mg[seg]) . qw -> alpha_s ----
    float ps[2][2];
    #pragma unroll
    for (int mt = 0; mt < 2; ++mt) { ps[mt][0] = 0.f; ps[mt][1] = 0.f; }
    int rowA = R0 + (lane >> 2);
    int sg[2][2];
    #pragma unroll
    for (int mt = 0; mt < 2; ++mt) {
        sg[mt][0] = seg_s[rowA + mt * 16];
        sg[mt][1] = seg_s[rowA + mt * 16 + 8];
    }
    #pragma unroll
    for (int nt = 0; nt < 8; ++nt) {
        int c = C0 + nt * 8 + (lane & 3) * 2;
        float2 bv = *(const float2*)&b2[c];
        float2 qv = *(const float2*)&qw[c];
        #pragma unroll
        for (int mt = 0; mt < 2; ++mt) {
            float2 m1 = *(const float2*)&g_mg[(size_t)sg[mt][0] * H + c];
            float2 m2 = *(const float2*)&g_mg[(size_t)sg[mt][1] * H + c];
            float z0 = acc[mt][nt][0] + bv.x + m1.x;
            float z1 = acc[mt][nt][1] + bv.y + m1.y;
            float z2 = acc[mt][nt][2] + bv.x + m2.x;
            float z3 = acc[mt][nt][3] + bv.y + m2.y;
            float g0 = 1.f / (1.f + __expf(-z0));
            float g1 = 1.f / (1.f + __expf(-z1));
            float g2 = 1.f / (1.f + __expf(-z2));
            float g3 = 1.f / (1.f + __expf(-z3));
            ps[mt][0] = fmaf(g0, qv.x, fmaf(g1, qv.y, ps[mt][0]));
            ps[mt][1] = fmaf(g2, qv.x, fmaf(g3, qv.y, ps[mt][1]));
        }
    }
    #pragma unroll
    for (int mt = 0; mt < 2; ++mt)
        #pragma unroll
        for (int hf = 0; hf < 2; ++hf) {
            ps[mt][hf] += __shfl_down_sync(0xffffffffu, ps[mt][hf], 2, 4);
            ps[mt][hf] += __shfl_down_sync(0xffffffffu, ps[mt][hf], 1, 4);
        }
    int cg = wid & 3;
    if ((lane & 3) == 0) {
        #pragma unroll
        for (int mt = 0; mt < 2; ++mt) {
            partm[(rowA + mt * 16) * 4 + cg]     = ps[mt][0];
            partm[(rowA + mt * 16 + 8) * 4 + cg] = ps[mt][1];
        }
    }
    __syncthreads();
    if (tid < TM) {
        float a = (partm[tid * 4 + 0] + partm[tid * 4 + 1]) +
                  (partm[tid * 4 + 2] + partm[tid * 4 + 3]);
        alpha_s[tid] = a + qb[0];
    }
    __syncthreads();

    // ---- fused finisher: out[seg] += alpha * hidden (fp32, from gmem) ----
    {
        int c = tid;
        int nrows = T - t0; if (nrows > TM) nrows = TM;
        float accs = 0.f;
        int cur = seg_s[0];
        for (int rb_ = 0; rb_ < nrows; rb_ += 8) {
            int m = nrows - rb_; if (m > 8) m = 8;
            float hv[8];
            #pragma unroll
            for (int i = 0; i < 8; ++i)
                if (i < m) hv[i] = hidden[(size_t)(t0 + rb_ + i) * H + c];
            #pragma unroll
            for (int i = 0; i < 8; ++i) {
                if (i < m) {
                    int sgr = seg_s[rb_ + i];
                    if (sgr != cur) {
                        atomicAdd(&out[(size_t)cur * H + c], accs);
                        accs = 0.f;
                        cur = sgr;
                    }
                    accs = fmaf(alpha_s[rb_ + i], hv[i], accs);
                }
            }
        }
        atomicAdd(&out[(size_t)cur * H + c], accs);
    }
}

// ---------------------------------------------------------------
extern "C" void kernel_launch(void* const* d_in, const int* in_sizes, int n_in,
                              void* d_out, int out_size) {
    const float* hidden      = (const float*)d_in[0];
    const float* pos_table   = (const float*)d_in[1];
    const float* W_pos       = (const float*)d_in[2];
    const float* b_pos       = (const float*)d_in[3];
    const float* W1          = (const float*)d_in[4];
    const float* b1          = (const float*)d_in[5];
    const float* W2          = (const float*)d_in[6];
    const float* b2          = (const float*)d_in[7];
    const float* qw          = (const float*)d_in[8];
    const float* qb          = (const float*)d_in[9];
    const int*   seq_len     = (const int*)d_in[10];
    const int*   reverse_pos = (const int*)d_in[11];

    int T    = in_sizes[0] / H;
    int nb   = in_sizes[10];
    int npos = in_sizes[1] / H;

    size_t smem_gemm = (size_t)(TM * SXH + 2 * 256 * SWH) * sizeof(__half);
    size_t smem_main = smem_gemm + (size_t)(TM * 5) * sizeof(float)
                     + (size_t)(2 * TM) * sizeof(int);
    cudaFuncSetAttribute(k_gemm_bias2, cudaFuncAttributeMaxDynamicSharedMemorySize, (int)smem_gemm);
    cudaFuncSetAttribute(k_main_mma,   cudaFuncAttributeMaxDynamicSharedMemorySize, (int)smem_main);

    int nblk_mg = (nb + TM - 1) / TM;
    int nblk_pp = (npos + TM - 1) / TM;

    k_scan<<<1, 1024>>>(seq_len, nb);
    dim3 tg(64, 4);
    k_transpose<<<tg, 256>>>(W_pos, W1, W2);
    k_mean_seg<<<nb, H>>>(hidden, (float*)d_out, nb);
    // combined: mg = mean@W1^T+b1  AND  posproj = pos_table@Wp_bot^T+b_pos
    k_gemm_bias2<<<nblk_mg + nblk_pp, NTHR, smem_gemm>>>(pos_table, b1, b_pos,
                                                         nb, npos, nblk_mg);
    k_main_mma<<<(T + TM - 1) / TM, NTHR, smem_main>>>(hidden, b2, qw, qb,
                                                       reverse_pos, (float*)d_out, T);
}